// round 1
// baseline (speedup 1.0000x reference)
#include <cuda_runtime.h>

// ---------------------------------------------------------------------------
// Multigrid F-cycle, 4096x4096, t=4 iterations.
//   CXW = CYW = DT/DX/2 = 0.05, DIAG = 1.
// Per iteration:
//   r1 = restrict( smooth_bc(v) )                 [fused, r_s[0] never used]
//   r2..r9 = restriction chain
//   e9 = r9; e_L = r_L - edgestencil(prolong(e_{L+1}), zero BC), L=8..1
//   v  = -edgestencil( v - prolong(e1), replicate BC )   [center cancels]
// ---------------------------------------------------------------------------

#define N0 4096
#define CW 0.05f

// scratch (device globals; allocation in kernel_launch is forbidden)
static __device__ float g_v [N0 * N0];        // ping-pong partner for d_out
static __device__ float g_r1[2048 * 2048];
static __device__ float g_r2[1024 * 1024];
static __device__ float g_r3[ 512 *  512];
static __device__ float g_r4[ 256 *  256];
static __device__ float g_r5[ 128 *  128];
static __device__ float g_r6[  64 *   64];
static __device__ float g_r7[  32 *   32];
static __device__ float g_r8[  16 *   16];
static __device__ float g_r9[   8 *    8];
static __device__ float g_e1[2048 * 2048];
static __device__ float g_e2[1024 * 1024];
static __device__ float g_e3[ 512 *  512];
static __device__ float g_e4[ 256 *  256];
static __device__ float g_e5[ 128 *  128];
static __device__ float g_e6[  64 *   64];
static __device__ float g_e7[  32 *   32];
static __device__ float g_e8[  16 *   16];
// e9 == r9 (first correction step is exactly e = r9)

// clamped (replicate-BC) load from the fine grid
static __device__ __forceinline__ float vclamp(const float* __restrict__ v, int y, int x) {
    y = min(max(y, 0), N0 - 1);
    x = min(max(x, 0), N0 - 1);
    return __ldg(v + y * N0 + x);
}

// ---------------------------------------------------------------------------
// Kernel A: fused fine smooth (replicate BC) + 2x2 restriction -> r1 (2048^2)
// r(y,x) = v[y,x] + CW*(vc(y-1,x)-vc(y+1,x)) + CW*(vc(y,x-1)-vc(y,x+1))
// out[I,J] = 0.25 * (r(2I,2J)+r(2I,2J+1)+r(2I+1,2J)+r(2I+1,2J+1))
// ---------------------------------------------------------------------------
__global__ void k_smooth_restrict(const float* __restrict__ v, float* __restrict__ r1) {
    int J = blockIdx.x * blockDim.x + threadIdx.x;  // 0..2047
    int I = blockIdx.y * blockDim.y + threadIdx.y;  // 0..2047
    int y0 = 2 * I, y1 = y0 + 1;
    int x0 = 2 * J, x1 = x0 + 1;

    const float* row0 = v + y0 * N0;
    float c00 = __ldg(row0 + x0);
    float c01 = __ldg(row0 + x1);
    float c10 = __ldg(row0 + N0 + x0);
    float c11 = __ldg(row0 + N0 + x1);

    float t0 = vclamp(v, y0 - 1, x0), t1 = vclamp(v, y0 - 1, x1);
    float b0 = vclamp(v, y1 + 1, x0), b1 = vclamp(v, y1 + 1, x1);
    float l0 = vclamp(v, y0, x0 - 1), l1 = vclamp(v, y1, x0 - 1);
    float q0 = vclamp(v, y0, x1 + 1), q1 = vclamp(v, y1, x1 + 1);

    float s = (c00 + c01 + c10 + c11)
            + CW * ((t0 - c10) + (t1 - c11) + (c00 - b0) + (c01 - b1))   // y terms
            + CW * ((l0 - c01) + (c00 - q0) + (l1 - c11) + (c10 - q1));  // x terms
    r1[I * 2048 + J] = 0.25f * s;
}

// ---------------------------------------------------------------------------
// Restriction: 2x2 average, (2n x 2n) -> (n x n)
// ---------------------------------------------------------------------------
__global__ void k_restrict(const float* __restrict__ in, float* __restrict__ out, int n) {
    int J = blockIdx.x * blockDim.x + threadIdx.x;
    int I = blockIdx.y * blockDim.y + threadIdx.y;
    int n2 = 2 * n;
    const float* p = in + (2 * I) * n2 + 2 * J;
    out[I * n + J] = 0.25f * (__ldg(p) + __ldg(p + 1) + __ldg(p + n2) + __ldg(p + n2 + 1));
}

static __device__ __forceinline__ void restrict_strided(
    const float* __restrict__ in, float* __restrict__ out, int n, int tid, int nth) {
    int n2 = 2 * n;
    for (int idx = tid; idx < n * n; idx += nth) {
        int I = idx / n, J = idx - I * n;
        const float* p = in + (2 * I) * n2 + 2 * J;
        out[idx] = 0.25f * (p[0] + p[1] + p[n2] + p[n2 + 1]);
    }
}

// tail of the restriction chain, one block: r5->r6->r7->r8->r9
__global__ void k_restrict_tail() {
    int tid = threadIdx.x, nth = blockDim.x;
    restrict_strided(g_r5, g_r6, 64, tid, nth); __syncthreads();
    restrict_strided(g_r6, g_r7, 32, tid, nth); __syncthreads();
    restrict_strided(g_r7, g_r8, 16, tid, nth); __syncthreads();
    restrict_strided(g_r8, g_r9,  8, tid, nth);
}

// ---------------------------------------------------------------------------
// Correction (fused prolong, zero BC):
// e[I,J] = r[I,J] - CW*(ep(I-1,J)-ep(I+1,J)) - CW*(ep(I,J-1)-ep(I,J+1))
// where ep(a,b) = in-bounds ? ecoarse[a>>1, b>>1] : 0
// ---------------------------------------------------------------------------
static __device__ __forceinline__ float correct_val(
    const float* __restrict__ r, const float* __restrict__ ec, int n, int I, int J) {
    int nc = n >> 1;
    float up = (I > 0)     ? __ldg(ec + ((I - 1) >> 1) * nc + (J >> 1)) : 0.0f;
    float dn = (I < n - 1) ? __ldg(ec + ((I + 1) >> 1) * nc + (J >> 1)) : 0.0f;
    float lf = (J > 0)     ? __ldg(ec + (I >> 1) * nc + ((J - 1) >> 1)) : 0.0f;
    float rt = (J < n - 1) ? __ldg(ec + (I >> 1) * nc + ((J + 1) >> 1)) : 0.0f;
    return __ldg(r + I * n + J) - CW * (up - dn) - CW * (lf - rt);
}

__global__ void k_correct(const float* __restrict__ r, const float* __restrict__ ec,
                          float* __restrict__ e, int n) {
    int J = blockIdx.x * blockDim.x + threadIdx.x;
    int I = blockIdx.y * blockDim.y + threadIdx.y;
    e[I * n + J] = correct_val(r, ec, n, I, J);
}

static __device__ __forceinline__ void correct_strided(
    const float* __restrict__ r, const float* __restrict__ ec, float* __restrict__ e,
    int n, int tid, int nth) {
    for (int idx = tid; idx < n * n; idx += nth) {
        int I = idx / n, J = idx - I * n;
        e[idx] = correct_val(r, ec, n, I, J);
    }
}

// head of the correction chain, one block: e8(from r9) -> e7 -> e6 -> e5
__global__ void k_correct_tail() {
    int tid = threadIdx.x, nth = blockDim.x;
    correct_strided(g_r8, g_r9, g_e8,  16, tid, nth); __syncthreads();
    correct_strided(g_r7, g_e8, g_e7,  32, tid, nth); __syncthreads();
    correct_strided(g_r6, g_e7, g_e6,  64, tid, nth); __syncthreads();
    correct_strided(g_r5, g_e6, g_e5, 128, tid, nth);
}

// ---------------------------------------------------------------------------
// Final fused kernel:
//   vt(y,x)   = v[y,x] - e1[y>>1, x>>1]           (fused prolong + subtract)
//   out[y,x]  = -CW*(vt(y-1,x)-vt(y+1,x)) - CW*(vt(y,x-1)-vt(y,x+1))
// with replicate clamp at the fine-grid border (center term cancels exactly).
// ---------------------------------------------------------------------------
__global__ void k_final(const float* __restrict__ v, const float* __restrict__ e1,
                        float* __restrict__ out) {
    int x = blockIdx.x * blockDim.x + threadIdx.x;
    int y = blockIdx.y * blockDim.y + threadIdx.y;
    int ym = max(y - 1, 0), yp = min(y + 1, N0 - 1);
    int xm = max(x - 1, 0), xp = min(x + 1, N0 - 1);

    float vt_t = __ldg(v + ym * N0 + x) - __ldg(e1 + (ym >> 1) * 2048 + (x >> 1));
    float vt_b = __ldg(v + yp * N0 + x) - __ldg(e1 + (yp >> 1) * 2048 + (x >> 1));
    float vt_l = __ldg(v + y * N0 + xm) - __ldg(e1 + (y >> 1) * 2048 + (xm >> 1));
    float vt_r = __ldg(v + y * N0 + xp) - __ldg(e1 + (y >> 1) * 2048 + (xp >> 1));

    out[y * N0 + x] = -CW * (vt_t - vt_b) - CW * (vt_l - vt_r);
}

// ---------------------------------------------------------------------------
// Launch
// ---------------------------------------------------------------------------
extern "C" void kernel_launch(void* const* d_in, const int* in_sizes, int n_in,
                              void* d_out, int out_size) {
    const float* u = (const float*)d_in[0];
    float* out = (float*)d_out;

    float *pv, *pr1, *pr2, *pr3, *pr4, *pr5;
    float *pe1, *pe2, *pe3, *pe4, *pe5;
    cudaGetSymbolAddress((void**)&pv,  g_v);
    cudaGetSymbolAddress((void**)&pr1, g_r1);
    cudaGetSymbolAddress((void**)&pr2, g_r2);
    cudaGetSymbolAddress((void**)&pr3, g_r3);
    cudaGetSymbolAddress((void**)&pr4, g_r4);
    cudaGetSymbolAddress((void**)&pr5, g_r5);
    cudaGetSymbolAddress((void**)&pe1, g_e1);
    cudaGetSymbolAddress((void**)&pe2, g_e2);
    cudaGetSymbolAddress((void**)&pe3, g_e3);
    cudaGetSymbolAddress((void**)&pe4, g_e4);
    cudaGetSymbolAddress((void**)&pe5, g_e5);

    const dim3 B(32, 8);
    const dim3 gA(2048 / 32, 2048 / 8);
    const dim3 gF(N0 / 32, N0 / 8);
    auto gN = [](int n) { return dim3(n / 32, n / 8); };

    // t = 4 (fixed by the problem's setup_inputs)
    const float* vin[4]  = { u,   pv,  out, pv  };
    float*       vout[4] = { pv,  out, pv,  out };

    for (int it = 0; it < 4; ++it) {
        k_smooth_restrict<<<gA, B>>>(vin[it], pr1);
        k_restrict<<<gN(1024), B>>>(pr1, pr2, 1024);
        k_restrict<<<gN(512),  B>>>(pr2, pr3, 512);
        k_restrict<<<gN(256),  B>>>(pr3, pr4, 256);
        k_restrict<<<gN(128),  B>>>(pr4, pr5, 128);
        k_restrict_tail<<<1, 1024>>>();
        k_correct_tail<<<1, 1024>>>();
        k_correct<<<gN(256),  B>>>(pr4, pe5, pe4, 256);
        k_correct<<<gN(512),  B>>>(pr3, pe4, pe3, 512);
        k_correct<<<gN(1024), B>>>(pr2, pe3, pe2, 1024);
        k_correct<<<gN(2048), B>>>(pr1, pe2, pe1, 2048);
        k_final<<<gF, B>>>(vin[it], pe1, vout[it]);
    }
}

// round 2
// speedup vs baseline: 1.7630x; 1.7630x over previous
#include <cuda_runtime.h>

// ---------------------------------------------------------------------------
// Multigrid F-cycle, 4096x4096, t=4 iterations, 3 kernels per iteration.
//   CW = DT/DX/2 = 0.05, DIAG = 1.
//   k_down: v -> r1..r7  (fused fine smooth + full tile-local restrict chain)
//   k_mid : r7 -> r8,r9 -> e8 -> e7 (single block)
//   k_up  : e7 -> e6..e1 tiles in smem -> out = -edgestencil(v - prolong(e1))
// ---------------------------------------------------------------------------

#define N0 4096
#define CW 0.05f

static __device__ float g_v [N0 * N0];       // ping-pong partner for d_out
static __device__ float g_r1[2048 * 2048];
static __device__ float g_r2[1024 * 1024];
static __device__ float g_r3[ 512 *  512];
static __device__ float g_r4[ 256 *  256];
static __device__ float g_r5[ 128 *  128];
static __device__ float g_r6[  64 *   64];
static __device__ float g_r7[  32 *   32];
static __device__ float g_e7[  32 *   32];

static __device__ __forceinline__ float vclamp(const float* __restrict__ v, int y, int x) {
    y = min(max(y, 0), N0 - 1);
    x = min(max(x, 0), N0 - 1);
    return __ldg(v + (size_t)y * N0 + x);
}

// ---------------------------------------------------------------------------
// smem restriction step: sA (NA x NA, stride SA) -> sB (NB x NB, stride SB),
// also writes the NB x NB tile into global array g of width WB at (by*NB, bx*NB).
// ---------------------------------------------------------------------------
template<int NA, int SA, int NB, int SB, int WB>
static __device__ __forceinline__ void restr_step(const float* sA, float* sB,
                                                  float* __restrict__ g,
                                                  int bx, int by, int tid) {
    #pragma unroll 1
    for (int idx = tid; idx < NB * NB; idx += 256) {
        int I = idx / NB, J = idx - I * NB;
        const float* p = sA + (2 * I) * SA + 2 * J;
        float x = 0.25f * (p[0] + p[1] + p[SA] + p[SA + 1]);
        if (NB > 1) sB[I * SB + J] = x;
        g[(by * NB + I) * WB + (bx * NB + J)] = x;
    }
}

// ---------------------------------------------------------------------------
// Kernel 1: per block, 64x64 tile of r1 from v (replicate BC), then the full
// restriction chain down to a single r7 element. Grid (32,32), 256 threads.
// ---------------------------------------------------------------------------
__global__ __launch_bounds__(256) void k_down(const float* __restrict__ v) {
    __shared__ float s1[64 * 65];
    __shared__ float s2[32 * 33];
    __shared__ float s3[16 * 17];
    __shared__ float s4[ 8 *  9];
    __shared__ float s5[ 4 *  5];
    __shared__ float s6[ 2 *  3];

    int tid = threadIdx.x;
    int bx = blockIdx.x, by = blockIdx.y;
    int Jt = tid & 63, rg = tid >> 6;         // col in tile, row group (0..3)
    int Jg = (bx << 6) + Jt;
    int x0 = 2 * Jg;

    #pragma unroll 4
    for (int k = 0; k < 16; ++k) {
        int It = (k << 2) + rg;
        int Ig = (by << 6) + It;
        int y0 = 2 * Ig;

        const float* row0 = v + (size_t)y0 * N0;
        float c00 = __ldg(row0 + x0);
        float c01 = __ldg(row0 + x0 + 1);
        float c10 = __ldg(row0 + N0 + x0);
        float c11 = __ldg(row0 + N0 + x0 + 1);
        float t0 = vclamp(v, y0 - 1, x0),     t1 = vclamp(v, y0 - 1, x0 + 1);
        float b0 = vclamp(v, y0 + 2, x0),     b1 = vclamp(v, y0 + 2, x0 + 1);
        float l0 = vclamp(v, y0,     x0 - 1), l1 = vclamp(v, y0 + 1, x0 - 1);
        float q0 = vclamp(v, y0,     x0 + 2), q1 = vclamp(v, y0 + 1, x0 + 2);

        float s = (c00 + c01 + c10 + c11)
                + CW * ((t0 - c10) + (t1 - c11) + (c00 - b0) + (c01 - b1))
                + CW * ((l0 - c01) + (c00 - q0) + (l1 - c11) + (c10 - q1));
        float val = 0.25f * s;
        s1[It * 65 + Jt] = val;
        g_r1[Ig * 2048 + Jg] = val;
    }
    __syncthreads();

    restr_step<64, 65, 32, 33, 1024>(s1, s2, g_r2, bx, by, tid); __syncthreads();
    restr_step<32, 33, 16, 17,  512>(s2, s3, g_r3, bx, by, tid); __syncthreads();
    restr_step<16, 17,  8,  9,  256>(s3, s4, g_r4, bx, by, tid); __syncthreads();
    restr_step< 8,  9,  4,  5,  128>(s4, s5, g_r5, bx, by, tid); __syncthreads();
    restr_step< 4,  5,  2,  3,   64>(s5, s6, g_r6, bx, by, tid); __syncthreads();
    restr_step< 2,  3,  1,  1,   32>(s6, s6, g_r7, bx, by, tid);
}

// ---------------------------------------------------------------------------
// Kernel 2: single block. r7 -> r8 -> r9, then e8 = correct(r8, r9),
// e7 = correct(r7, e8). 256 threads.
// ---------------------------------------------------------------------------
__global__ __launch_bounds__(256) void k_mid() {
    __shared__ float s8[16 * 16];
    __shared__ float s9[ 8 *  8];
    __shared__ float e8[16 * 16];
    int tid = threadIdx.x;

    if (tid < 256) {
        int I = tid >> 4, J = tid & 15;
        const float* p = g_r7 + (2 * I) * 32 + 2 * J;
        s8[tid] = 0.25f * (p[0] + p[1] + p[32] + p[33]);
    }
    __syncthreads();
    if (tid < 64) {
        int I = tid >> 3, J = tid & 7;
        const float* p = s8 + (2 * I) * 16 + 2 * J;
        s9[tid] = 0.25f * (p[0] + p[1] + p[16] + p[17]);
    }
    __syncthreads();
    {
        int I = tid >> 4, J = tid & 15;
        float up = (I > 0)  ? s9[((I - 1) >> 1) * 8 + (J >> 1)] : 0.0f;
        float dn = (I < 15) ? s9[((I + 1) >> 1) * 8 + (J >> 1)] : 0.0f;
        float lf = (J > 0)  ? s9[(I >> 1) * 8 + ((J - 1) >> 1)] : 0.0f;
        float rt = (J < 15) ? s9[(I >> 1) * 8 + ((J + 1) >> 1)] : 0.0f;
        e8[tid] = s8[tid] - CW * (up - dn) - CW * (lf - rt);
    }
    __syncthreads();
    #pragma unroll
    for (int base = 0; base < 1024; base += 256) {
        int idx = base + tid;
        int I = idx >> 5, J = idx & 31;
        float up = (I > 0)  ? e8[((I - 1) >> 1) * 16 + (J >> 1)] : 0.0f;
        float dn = (I < 31) ? e8[((I + 1) >> 1) * 16 + (J >> 1)] : 0.0f;
        float lf = (J > 0)  ? e8[(I >> 1) * 16 + ((J - 1) >> 1)] : 0.0f;
        float rt = (J < 31) ? e8[(I >> 1) * 16 + ((J + 1) >> 1)] : 0.0f;
        g_e7[idx] = g_r7[idx] - CW * (up - dn) - CW * (lf - rt);
    }
}

// ---------------------------------------------------------------------------
// Kernel 3 helper: one correction level in smem.
// TC = block's cell count at this level, NL = global grid size at this level.
// Computes tile of size (TC+2)^2 with origin (by*TC-1, bx*TC-1) from global rL
// and the parent smem tile (size TC/2+2, origin (by*TC/2-1, bx*TC/2-1)).
// ---------------------------------------------------------------------------
template<int TC, int NL>
static __device__ __forceinline__ void correct_level(const float* __restrict__ rL,
                                                     const float* par, float* dst,
                                                     int bx, int by, int tid) {
    const int T  = TC + 2;
    const int TP = TC / 2 + 2;
    const int Or = by * TC - 1, Oc = bx * TC - 1;
    const int Pr = by * (TC / 2) - 1, Pc = bx * (TC / 2) - 1;
    #pragma unroll 1
    for (int idx = tid; idx < T * T; idx += 256) {
        int Ii = idx / T, Jj = idx - Ii * T;
        int I = Or + Ii, J = Oc + Jj;
        float e = 0.0f;
        if (I >= 0 && I < NL && J >= 0 && J < NL) {
            int pc = (J >> 1) - Pc;
            int pr = (I >> 1) - Pr;
            float up = (I > 0)      ? par[(((I - 1) >> 1) - Pr) * TP + pc] : 0.0f;
            float dn = (I < NL - 1) ? par[(((I + 1) >> 1) - Pr) * TP + pc] : 0.0f;
            float lf = (J > 0)      ? par[pr * TP + (((J - 1) >> 1) - Pc)] : 0.0f;
            float rt = (J < NL - 1) ? par[pr * TP + (((J + 1) >> 1) - Pc)] : 0.0f;
            e = __ldg(rL + I * NL + J) - CW * (up - dn) - CW * (lf - rt);
        }
        dst[idx] = e;
    }
}

// ---------------------------------------------------------------------------
// Kernel 3: per block, 128x128 output tile. Builds e6..e1 tiles in smem, then
// out = -edgestencil(v - prolong(e1)) with replicate BC, float4 I/O.
// Grid (32,32), 256 threads.
// ---------------------------------------------------------------------------
__global__ __launch_bounds__(256) void k_up(const float* __restrict__ v,
                                            float* __restrict__ out) {
    __shared__ float se7[ 3 *  3];
    __shared__ float se6[ 4 *  4];
    __shared__ float se5[ 6 *  6];
    __shared__ float se4[10 * 10];
    __shared__ float se3[18 * 18];
    __shared__ float se2[34 * 34];
    __shared__ float se1[66 * 66];

    int tid = threadIdx.x;
    int bx = blockIdx.x, by = blockIdx.y;

    if (tid < 9) {
        int I = by - 1 + tid / 3, J = bx - 1 + tid % 3;
        se7[tid] = (I >= 0 && I < 32 && J >= 0 && J < 32) ? __ldg(g_e7 + I * 32 + J) : 0.0f;
    }
    __syncthreads();
    correct_level< 2,   64>(g_r6, se7, se6, bx, by, tid); __syncthreads();
    correct_level< 4,  128>(g_r5, se6, se5, bx, by, tid); __syncthreads();
    correct_level< 8,  256>(g_r4, se5, se4, bx, by, tid); __syncthreads();
    correct_level<16,  512>(g_r3, se4, se3, bx, by, tid); __syncthreads();
    correct_level<32, 1024>(g_r2, se3, se2, bx, by, tid); __syncthreads();
    correct_level<64, 2048>(g_r1, se2, se1, bx, by, tid); __syncthreads();

    // final update: out[y, x..x+3]
    const int o1r = 64 * by - 1, o1c = 64 * bx - 1;
    int fc = tid & 31, rg = tid >> 5;
    int x  = (bx << 7) + (fc << 2);
    int ec0 = (x >> 1) - o1c;
    int ecL = (max(x - 1, 0) >> 1) - o1c;
    int ecR = (min(x + 4, N0 - 1) >> 1) - o1c;

    #pragma unroll 4
    for (int k = 0; k < 16; ++k) {
        int y = (by << 7) + rg + (k << 3);
        int ym = max(y - 1, 0), yp = min(y + 1, N0 - 1);

        float4 top = *(const float4*)(v + (size_t)ym * N0 + x);
        float4 bot = *(const float4*)(v + (size_t)yp * N0 + x);
        float4 mid = *(const float4*)(v + (size_t)y  * N0 + x);
        float  lf  = __ldg(v + (size_t)y * N0 + max(x - 1, 0));
        float  rt  = __ldg(v + (size_t)y * N0 + min(x + 4, N0 - 1));

        int ert = (ym >> 1) - o1r;
        int erm = (y  >> 1) - o1r;
        int erb = (yp >> 1) - o1r;

        float et0 = se1[ert * 66 + ec0], et1 = se1[ert * 66 + ec0 + 1];
        float eb0 = se1[erb * 66 + ec0], eb1 = se1[erb * 66 + ec0 + 1];
        float em0 = se1[erm * 66 + ec0], em1 = se1[erm * 66 + ec0 + 1];
        float emL = se1[erm * 66 + ecL], emR = se1[erm * 66 + ecR];

        float4 o;
        o.x = -CW * ((top.x - et0) - (bot.x - eb0)) - CW * ((lf    - emL) - (mid.y - em0));
        o.y = -CW * ((top.y - et0) - (bot.y - eb0)) - CW * ((mid.x - em0) - (mid.z - em1));
        o.z = -CW * ((top.z - et1) - (bot.z - eb1)) - CW * ((mid.y - em0) - (mid.w - em1));
        o.w = -CW * ((top.w - et1) - (bot.w - eb1)) - CW * ((mid.z - em1) - (rt    - emR));
        *(float4*)(out + (size_t)y * N0 + x) = o;
    }
}

// ---------------------------------------------------------------------------
// Launch: 3 kernels per iteration, 4 iterations.
// ---------------------------------------------------------------------------
extern "C" void kernel_launch(void* const* d_in, const int* in_sizes, int n_in,
                              void* d_out, int out_size) {
    const float* u = (const float*)d_in[0];
    float* out = (float*)d_out;

    float* pv;
    cudaGetSymbolAddress((void**)&pv, g_v);

    const dim3 G(32, 32);
    const float* vin[4]  = { u,   pv,  out, pv  };
    float*       vout[4] = { pv,  out, pv,  out };

    for (int it = 0; it < 4; ++it) {
        k_down<<<G, 256>>>(vin[it]);
        k_mid<<<1, 256>>>();
        k_up<<<G, 256>>>(vin[it], vout[it]);
    }
}